// round 6
// baseline (speedup 1.0000x reference)
#include <cuda_runtime.h>
#include <math.h>

#define SEQ  40
#define H    4096
#define OUT  128
#define NBLK 256
#define NTHR 512
#define JPB  (H / NBLK)     // 16 hidden indices per block
#define ROWS (4 * H)        // 16384 gate rows
#define RQ4  (H / 16)       // 256 uint4 (16 int8 weights) per row

// ---- persistent device state (no allocations allowed) ----
__device__ float    g_h[H];                                      // fp32 h (final step only)
__device__ unsigned g_hq[2][H / 2];                              // ping-pong s16x2 packed h
__device__ float    g_scale[ROWS];                               // per-row dequant scale
__device__ __align__(256) unsigned g_wq[(size_t)ROWS * (H / 4)]; // 67 MB SIGNED s8 weights
__device__ unsigned g_stamp[NBLK];                               // per-block step stamps

// ---------------- int8 quantization prologue (signed via XOR 0x80) ----------------
__global__ __launch_bounds__(256) void quant_kernel(const float* __restrict__ w_hh) {
    const int warp = threadIdx.x >> 5, lane = threadIdx.x & 31;
    const int r = blockIdx.x * 8 + warp;
    const float4* row = (const float4*)(w_hh + (size_t)r * H);
    float mx = 0.0f;
    #pragma unroll 8
    for (int c = lane; c < H / 4; c += 32) {
        float4 v = __ldg(row + c);
        mx = fmaxf(mx, fmaxf(fmaxf(fabsf(v.x), fabsf(v.y)),
                             fmaxf(fabsf(v.z), fabsf(v.w))));
    }
    #pragma unroll
    for (int o = 16; o > 0; o >>= 1) mx = fmaxf(mx, __shfl_xor_sync(0xffffffffu, mx, o));
    const float inv = (mx > 0.0f) ? 127.0f / mx : 0.0f;
    if (lane == 0) g_scale[r] = mx * (1.0f / 127.0f);

    uint4* dst = (uint4*)g_wq + (size_t)r * RQ4;
    for (int c = lane; c < RQ4; c += 32) {
        unsigned m[16];
        #pragma unroll
        for (int q = 0; q < 4; ++q) {
            float4 v = __ldg(row + 4 * c + q);
            m[4 * q + 0] = __float_as_uint(fmaf(v.x, inv, 128.0f) + 8388608.0f);
            m[4 * q + 1] = __float_as_uint(fmaf(v.y, inv, 128.0f) + 8388608.0f);
            m[4 * q + 2] = __float_as_uint(fmaf(v.z, inv, 128.0f) + 8388608.0f);
            m[4 * q + 3] = __float_as_uint(fmaf(v.w, inv, 128.0f) + 8388608.0f);
        }
        uint4 o;
        #pragma unroll
        for (int q = 0; q < 4; ++q) {
            unsigned t0 = __byte_perm(m[4 * q + 0], m[4 * q + 1], 0x0040);
            unsigned t1 = __byte_perm(m[4 * q + 2], m[4 * q + 3], 0x0040);
            // biased u8 -> signed s8 (q = biased - 128) via XOR of sign bit
            ((unsigned*)&o)[q] = __byte_perm(t0, t1, 0x5410) ^ 0x80808080u;
        }
        dst[c] = o;
    }
}

// ---------------- per-warp matvec: 4 consecutive rows, dp2a (s16 h x s8 w) ----------------
__device__ __forceinline__ void warp_rows4(const uint4 (&hq4)[2][260],
                                           int wid, int lane, int j0,
                                           float (&gsm)[4][JPB]) {
    const int rloc0 = wid * 4;
    const int gate  = rloc0 >> 4;
    const int jj0   = rloc0 & 15;
    const int grow0 = gate * H + j0 + jj0;
    const uint4* base = (const uint4*)g_wq + (size_t)grow0 * RQ4;

    int acc[4] = {0, 0, 0, 0};          // exact s32; per-lane max 127*32767*128 < 2^31

    uint4 wc[4], wn[4];
    #pragma unroll
    for (int rr = 0; rr < 4; ++rr) wc[rr] = __ldg(base + rr * RQ4 + lane);

    #pragma unroll
    for (int it = 0; it < RQ4 / 32; ++it) {      // 8 iterations, 16 weights/row each
        const int c = it * 32 + lane;
        if (it < RQ4 / 32 - 1) {
            #pragma unroll
            for (int rr = 0; rr < 4; ++rr) wn[rr] = __ldg(base + rr * RQ4 + c + 32);
        }
        const uint4 ha = hq4[0][c];     // h pairs 8c .. 8c+3  (h[16c..16c+7])
        const uint4 hb = hq4[1][c];     // h pairs 8c+4 .. 8c+7 (h[16c+8..16c+15])
        const int hp[8] = {(int)ha.x, (int)ha.y, (int)ha.z, (int)ha.w,
                           (int)hb.x, (int)hb.y, (int)hb.z, (int)hb.w};
        #pragma unroll
        for (int rr = 0; rr < 4; ++rr) {
            int a = acc[rr];
            #pragma unroll
            for (int q = 0; q < 4; ++q) {
                const int w = (int)((const unsigned*)&wc[rr])[q];  // 4 s8 = h[16c+4q..+3]
                a = __dp2a_lo(hp[2 * q + 0], w, a);                // bytes 0,1
                a = __dp2a_hi(hp[2 * q + 1], w, a);                // bytes 2,3
            }
            acc[rr] = a;
        }
        #pragma unroll
        for (int rr = 0; rr < 4; ++rr) wc[rr] = wn[rr];
    }
    #pragma unroll
    for (int rr = 0; rr < 4; ++rr) {
        float a = __int2float_rn(acc[rr]);       // convert before reduce: no s32 overflow
        #pragma unroll
        for (int o = 16; o > 0; o >>= 1) a += __shfl_down_sync(0xffffffffu, a, o);
        if (lane == 0)
            gsm[gate][jj0 + rr] = a * (g_scale[grow0 + rr] * (1.0f / 32767.0f));
    }
}

// ---------------- persistent LSTM kernel ----------------
__global__ __launch_bounds__(NTHR, 2)
void lstm_persistent_kernel(const float* __restrict__ x,
                            const float* __restrict__ w_ih,
                            const float* __restrict__ b_ih,
                            const float* __restrict__ b_hh,
                            const float* __restrict__ dense_w,
                            const float* __restrict__ dense_b,
                            float* __restrict__ out) {
    __shared__ uint4 hq4[2][260];      // de-interleaved packed h_{t-1} (conflict-free)
    __shared__ float gsm[4][JPB];
    __shared__ float c_s[JPB];
    __shared__ float hnew[JPB];
    __shared__ float red[NTHR / 32];

    const int tid  = threadIdx.x;
    const int lane = tid & 31;
    const int wid  = tid >> 5;
    const int j0   = blockIdx.x * JPB;

    // Monotonic stamp base (device globals persist across graph replays)
    const unsigned base = *(volatile unsigned*)&g_stamp[blockIdx.x];

    if (tid < JPB) c_s[tid] = 0.0f;

    for (int t = 0; t < SEQ; ++t) {
        if (t > 0) {
            // wait until every block has published h_{t-1} (stamp >= base+t)
            const unsigned target = base + (unsigned)t;
            for (;;) {
                int ok = 1;
                if (tid < NBLK)
                    ok = (*(volatile unsigned*)&g_stamp[tid] - base) >= (unsigned)t;
                if (__syncthreads_and(ok)) break;
            }
            __threadfence();   // acquire

            // stage packed h into smem, de-interleaved: uint4 u -> hq4[u&1][u>>1]
            const uint4* gq = (const uint4*)g_hq[(t - 1) & 1];
            const uint4 v = gq[tid];                 // 512 uint4 total
            hq4[tid & 1][tid >> 1] = v;
            __syncthreads();

            warp_rows4(hq4, wid, lane, j0, gsm);
            (void)target;
        }
        __syncthreads();

        if (tid < JPB) {
            const int   j  = j0 + tid;
            const float xt = x[t];
            float v[4];
            #pragma unroll
            for (int g = 0; g < 4; ++g) {
                const int row = g * H + j;
                const float dot = (t > 0) ? gsm[g][tid] : 0.0f;
                v[g] = fmaf(w_ih[row], xt, b_ih[row] + b_hh[row]) + dot;
            }
            const float ig = 1.0f / (1.0f + expf(-v[0]));
            const float fg = 1.0f / (1.0f + expf(-v[1]));
            const float gg = tanhf(v[2]);
            const float og = 1.0f / (1.0f + expf(-v[3]));
            const float c  = fg * c_s[tid] + ig * gg;
            c_s[tid] = c;
            const float h = og * tanhf(c);
            hnew[tid] = h;
            if (t == SEQ - 1) g_h[j] = h;            // fp32 only needed for dense
        }
        __syncthreads();

        // pack 16 h values -> 8 s16x2 words and publish
        if (tid < JPB / 2) {
            const int q0 = __float2int_rn(hnew[2 * tid]     * 32767.0f);
            const int q1 = __float2int_rn(hnew[2 * tid + 1] * 32767.0f);
            g_hq[t & 1][j0 / 2 + tid] = __byte_perm((unsigned)q0, (unsigned)q1, 0x5410);
        }
        __syncthreads();
        if (tid == 0) {
            __threadfence();                          // release h before stamp
            *(volatile unsigned*)&g_stamp[blockIdx.x] = base + (unsigned)(t + 1);
        }
    }

    // final sync: ensure all blocks published h_last before dense reads it
    for (;;) {
        int ok = 1;
        if (tid < NBLK)
            ok = (*(volatile unsigned*)&g_stamp[tid] - base) >= (unsigned)SEQ;
        if (__syncthreads_and(ok)) break;
    }
    __threadfence();

    // Dense epilogue: blocks 0..127 each compute one output row (fp32).
    if (blockIdx.x < OUT) {
        const float* hw = g_h;
        const float* wr = dense_w + (size_t)blockIdx.x * H;
        float acc = 0.0f;
        #pragma unroll
        for (int k = tid; k < H; k += NTHR)
            acc += wr[k] * hw[k];
        #pragma unroll
        for (int o = 16; o > 0; o >>= 1)
            acc += __shfl_down_sync(0xffffffffu, acc, o);
        if (lane == 0) red[wid] = acc;
        __syncthreads();
        if (tid == 0) {
            float s = 0.0f;
            #pragma unroll
            for (int w = 0; w < NTHR / 32; ++w) s += red[w];
            out[blockIdx.x] = s + dense_b[blockIdx.x];
        }
    }
}

extern "C" void kernel_launch(void* const* d_in, const int* in_sizes, int n_in,
                              void* d_out, int out_size) {
    const float* x       = (const float*)d_in[0];
    const float* w_ih    = (const float*)d_in[1];
    const float* w_hh    = (const float*)d_in[2];
    const float* b_ih    = (const float*)d_in[3];
    const float* b_hh    = (const float*)d_in[4];
    const float* dense_w = (const float*)d_in[5];
    const float* dense_b = (const float*)d_in[6];

    quant_kernel<<<ROWS / 8, 256>>>(w_hh);
    lstm_persistent_kernel<<<NBLK, NTHR>>>(x, w_ih, b_ih, b_hh,
                                           dense_w, dense_b, (float*)d_out);
}

// round 8
// speedup vs baseline: 1.2544x; 1.2544x over previous
#include <cuda_runtime.h>
#include <math.h>

#define SEQ   40
#define H     4096
#define OUT   128
#define NBLK  128
#define NCONS 512                 // consumer threads (16 warps)
#define NTHR  544                 // + 1 producer warp
#define JPB   32                  // hidden indices per block
#define RPB   128                 // rows per block (4 gates x 32)
#define ROWS  (4 * H)
#define CHUNK_BYTES 32768         // 128 rows x 256B K-slice
#define NCHUNK 16                 // chunks per step (16 x 256B = 4KB row)
#define NSTAGE 6
#define BLOCK_WQ (RPB * H)        // 512KB of s8 weights per block
#define OFF_HQ  (NSTAGE * CHUNK_BYTES)       // packed h: 2048 u32 = 8KB
#define OFF_MB  (OFF_HQ + 8192)              // 12 mbarriers
#define DSM_BYTES (OFF_MB + 128)

// ---- persistent device state (no allocations allowed) ----
__device__ float    g_h[H];                                      // fp32 h_last for dense
__device__ unsigned g_hq[2][H / 2];                              // ping-pong s16x2 h
__device__ float    g_scale[ROWS];                               // per-row dequant scale
__device__ __align__(256) unsigned char g_wq[(size_t)NBLK * BLOCK_WQ]; // 67MB s8, per-block chunked
__device__ __align__(16) unsigned g_stamp[NBLK];                 // per-block step stamps

// ---------------- smem / mbarrier helpers ----------------
__device__ __forceinline__ unsigned smem_u32(const void* p) {
    return (unsigned)__cvta_generic_to_shared(p);
}
__device__ __forceinline__ void mbar_init(unsigned a, unsigned cnt) {
    asm volatile("mbarrier.init.shared.b64 [%0], %1;" :: "r"(a), "r"(cnt) : "memory");
}
__device__ __forceinline__ void mbar_expect_tx(unsigned a, unsigned bytes) {
    asm volatile("mbarrier.arrive.expect_tx.shared.b64 _, [%0], %1;"
                 :: "r"(a), "r"(bytes) : "memory");
}
__device__ __forceinline__ void mbar_arrive(unsigned a) {
    asm volatile("mbarrier.arrive.shared.b64 _, [%0];" :: "r"(a) : "memory");
}
__device__ __forceinline__ void mbar_wait(unsigned a, unsigned parity) {
    asm volatile(
        "{\n\t.reg .pred P;\n"
        "WL%=:\n\tmbarrier.try_wait.parity.shared.b64 P, [%0], %1;\n"
        "\t@P bra WD%=;\n\tbra WL%=;\nWD%=:\n\t}"
        :: "r"(a), "r"(parity) : "memory");
}
__device__ __forceinline__ void bulk_g2s(unsigned dst, const void* src,
                                         unsigned bytes, unsigned mbar) {
    asm volatile(
        "cp.async.bulk.shared::cta.global.mbarrier::complete_tx::bytes [%0], [%1], %2, [%3];"
        :: "r"(dst), "l"(src), "r"(bytes), "r"(mbar) : "memory");
}
#define CONS_BAR() asm volatile("bar.sync 1, 512;" ::: "memory")

// ---------------- single-pass quant: one block per row, transposed chunked output ----------------
__global__ __launch_bounds__(256) void quant_kernel(const float* __restrict__ w_hh) {
    __shared__ float wmax[8];
    const int r   = blockIdx.x;                 // global gate row (gate*H + j)
    const int tid = threadIdx.x;
    const int lane = tid & 31, wid = tid >> 5;

    const float4* rp = (const float4*)(w_hh + (size_t)r * H) + tid * 4;
    float4 v0 = __ldg(rp), v1 = __ldg(rp + 1), v2 = __ldg(rp + 2), v3 = __ldg(rp + 3);

    float m = 0.0f;
    const float4 vs[4] = {v0, v1, v2, v3};
    #pragma unroll
    for (int q = 0; q < 4; ++q)
        m = fmaxf(m, fmaxf(fmaxf(fabsf(vs[q].x), fabsf(vs[q].y)),
                           fmaxf(fabsf(vs[q].z), fabsf(vs[q].w))));
    #pragma unroll
    for (int o = 16; o > 0; o >>= 1) m = fmaxf(m, __shfl_xor_sync(0xffffffffu, m, o));
    if (lane == 0) wmax[wid] = m;
    __syncthreads();
    float mx = wmax[0];
    #pragma unroll
    for (int w = 1; w < 8; ++w) mx = fmaxf(mx, wmax[w]);
    if (tid == 0) g_scale[r] = mx * (1.0f / 127.0f);
    const float inv = (mx > 0.0f) ? 127.0f / mx : 0.0f;

    // quantize 16 values: single FFMA to 2^23+128+q (exact RN), low byte = q+128
    unsigned b[16];
    #pragma unroll
    for (int q = 0; q < 4; ++q) {
        b[4 * q + 0] = __float_as_uint(fmaf(vs[q].x, inv, 8388736.0f));
        b[4 * q + 1] = __float_as_uint(fmaf(vs[q].y, inv, 8388736.0f));
        b[4 * q + 2] = __float_as_uint(fmaf(vs[q].z, inv, 8388736.0f));
        b[4 * q + 3] = __float_as_uint(fmaf(vs[q].w, inv, 8388736.0f));
    }
    uint4 o;
    #pragma unroll
    for (int q = 0; q < 4; ++q) {
        unsigned t0 = __byte_perm(b[4 * q + 0], b[4 * q + 1], 0x0040);
        unsigned t1 = __byte_perm(b[4 * q + 2], b[4 * q + 3], 0x0040);
        ((unsigned*)&o)[q] = __byte_perm(t0, t1, 0x5410) ^ 0x80808080u; // biased->signed
    }
    // destination: [block B][chunk][rowloc][256B], thread covers cols 16tid..16tid+15
    const int j = r & (H - 1);
    const int gate = r >> 12;
    const int B = j >> 5;
    const int rowloc = gate * 32 + (j & 31);
    const size_t off = (size_t)B * BLOCK_WQ + (size_t)(tid >> 4) * CHUNK_BYTES
                     + rowloc * 256 + (tid & 15) * 16;
    *(uint4*)(g_wq + off) = o;
}

// ---------------- persistent warp-specialized LSTM kernel ----------------
__global__ __launch_bounds__(NTHR, 1)
void lstm_persistent_kernel(const float* __restrict__ x,
                            const float* __restrict__ w_ih,
                            const float* __restrict__ b_ih,
                            const float* __restrict__ b_hh,
                            const float* __restrict__ dense_w,
                            const float* __restrict__ dense_b,
                            float* __restrict__ out) {
    extern __shared__ char dsm[];
    __shared__ float gsm[4][JPB];
    __shared__ float c_s[JPB];
    __shared__ float hnew[JPB];
    __shared__ float red[16];

    const int tid  = threadIdx.x;
    const int lane = tid & 31;
    const int wid  = tid >> 5;
    const unsigned mb = smem_u32(dsm + OFF_MB);   // full[s]=mb+8s, empty[s]=mb+48+8s

    if (tid == 0) {
        #pragma unroll
        for (int s = 0; s < NSTAGE; ++s) {
            mbar_init(mb + 8 * s, 1);             // full: 1 producer arrival (expect_tx)
            mbar_init(mb + 48 + 8 * s, 16);       // empty: 16 consumer-warp arrivals
        }
    }
    __syncthreads();                              // all 544 threads

    // ---------------- producer warp (warp 16) ----------------
    if (wid == 16) {
        if (lane == 0) {
            int ps = 0; unsigned pp = 1;          // producer phase starts flipped
            const unsigned char* src = g_wq + (size_t)blockIdx.x * BLOCK_WQ;
            const unsigned dst0 = smem_u32(dsm);
            for (int g = 0; g < (SEQ - 1) * NCHUNK; ++g) {
                mbar_wait(mb + 48 + 8 * ps, pp);
                mbar_expect_tx(mb + 8 * ps, CHUNK_BYTES);
                bulk_g2s(dst0 + ps * CHUNK_BYTES,
                         src + (size_t)(g & (NCHUNK - 1)) * CHUNK_BYTES,
                         CHUNK_BYTES, mb + 8 * ps);
                if (++ps == NSTAGE) { ps = 0; pp ^= 1; }
            }
        }
        return;                                   // producer warp exits
    }

    // ---------------- consumers (warps 0..15) ----------------
    const int j0 = blockIdx.x * JPB;
    const unsigned base = *(volatile unsigned*)&g_stamp[blockIdx.x];
    unsigned* hq = (unsigned*)(dsm + OFF_HQ);
    if (tid < JPB) c_s[tid] = 0.0f;

    int cs = 0; unsigned cpar = 0;                // consumer ring cursor

    for (int t = 0; t < SEQ; ++t) {
        if (t > 0) {
            // grid barrier: warp 0 polls all 128 stamps (4/lane via one v4 load)
            if (wid == 0) {
                const unsigned* sp = g_stamp + lane * 4;
                for (;;) {
                    unsigned s0, s1, s2, s3;
                    asm volatile("ld.volatile.global.v4.u32 {%0,%1,%2,%3}, [%4];"
                                 : "=r"(s0), "=r"(s1), "=r"(s2), "=r"(s3) : "l"(sp));
                    const bool ok = (s0 - base) >= (unsigned)t && (s1 - base) >= (unsigned)t
                                 && (s2 - base) >= (unsigned)t && (s3 - base) >= (unsigned)t;
                    if (__all_sync(0xffffffffu, ok)) break;
                }
                __threadfence();
            }
            CONS_BAR();
            // stage packed h_{t-1}
            ((uint4*)hq)[tid] = ((const uint4*)g_hq[(t - 1) & 1])[tid];
            CONS_BAR();

            // mainloop over 16 chunks. Warp w owns rows 8w..8w+7.
            // Lane l covers cols 8l..8l+7 of each row (uint2 weights, uint4 h).
            int acc[8] = {0, 0, 0, 0, 0, 0, 0, 0};
            for (int c = 0; c < NCHUNK; ++c) {
                mbar_wait(mb + 8 * cs, cpar);
                const char* chk = dsm + cs * CHUNK_BYTES + wid * 8 * 256 + lane * 8;
                const uint4 hv = *(const uint4*)(hq + 128 * c + 4 * lane);
                #pragma unroll
                for (int rr = 0; rr < 8; ++rr) {
                    const uint2 wv = *(const uint2*)(chk + rr * 256);
                    int a = acc[rr];
                    a = __dp2a_lo((int)hv.x, (int)wv.x, a);   // cols 8l+0,1
                    a = __dp2a_hi((int)hv.y, (int)wv.x, a);   // cols 8l+2,3
                    a = __dp2a_lo((int)hv.z, (int)wv.y, a);   // cols 8l+4,5
                    a = __dp2a_hi((int)hv.w, (int)wv.y, a);   // cols 8l+6,7
                    acc[rr] = a;
                }
                __syncwarp();
                if (lane == 0) mbar_arrive(mb + 48 + 8 * cs);   // release stage
                if (++cs == NSTAGE) { cs = 0; cpar ^= 1; }
            }
            // reduce 8 rows
            #pragma unroll
            for (int rr = 0; rr < 8; ++rr) {
                float a = __int2float_rn(acc[rr]);
                #pragma unroll
                for (int o = 16; o > 0; o >>= 1)
                    a += __shfl_down_sync(0xffffffffu, a, o);
                if (lane == 0) {
                    const int rloc = wid * 8 + rr;
                    const int gate = rloc >> 5, jj = rloc & 31;
                    gsm[gate][jj] = a * (g_scale[gate * H + j0 + jj] * (1.0f / 32767.0f));
                }
            }
        }
        CONS_BAR();

        if (tid < JPB) {
            const int   j  = j0 + tid;
            const float xt = x[t];
            float v[4];
            #pragma unroll
            for (int g = 0; g < 4; ++g) {
                const int row = g * H + j;
                const float dot = (t > 0) ? gsm[g][tid] : 0.0f;
                v[g] = fmaf(w_ih[row], xt, b_ih[row] + b_hh[row]) + dot;
            }
            const float ig = 1.0f / (1.0f + expf(-v[0]));
            const float fg = 1.0f / (1.0f + expf(-v[1]));
            const float gg = tanhf(v[2]);
            const float og = 1.0f / (1.0f + expf(-v[3]));
            const float c  = fg * c_s[tid] + ig * gg;
            c_s[tid] = c;
            const float h = og * tanhf(c);
            hnew[tid] = h;
            if (t == SEQ - 1) g_h[j] = h;
        }
        CONS_BAR();
        if (tid < JPB / 2) {
            const int q0 = __float2int_rn(hnew[2 * tid]     * 32767.0f);
            const int q1 = __float2int_rn(hnew[2 * tid + 1] * 32767.0f);
            g_hq[t & 1][j0 / 2 + tid] = __byte_perm((unsigned)q0, (unsigned)q1, 0x5410);
        }
        CONS_BAR();
        if (tid == 0) {
            __threadfence();
            *(volatile unsigned*)&g_stamp[blockIdx.x] = base + (unsigned)(t + 1);
        }
    }

    // final sync: all blocks published h_last
    if (wid == 0) {
        const unsigned* sp = g_stamp + lane * 4;
        for (;;) {
            unsigned s0, s1, s2, s3;
            asm volatile("ld.volatile.global.v4.u32 {%0,%1,%2,%3}, [%4];"
                         : "=r"(s0), "=r"(s1), "=r"(s2), "=r"(s3) : "l"(sp));
            const bool ok = (s0 - base) >= SEQ && (s1 - base) >= SEQ
                         && (s2 - base) >= SEQ && (s3 - base) >= SEQ;
            if (__all_sync(0xffffffffu, ok)) break;
        }
        __threadfence();
    }
    CONS_BAR();

    // dense epilogue: block b computes out[b] (NBLK == OUT)
    {
        const float* hw = g_h;
        const float* wr = dense_w + (size_t)blockIdx.x * H;
        float acc = 0.0f;
        #pragma unroll
        for (int k = tid; k < H; k += NCONS)
            acc += wr[k] * hw[k];
        #pragma unroll
        for (int o = 16; o > 0; o >>= 1)
            acc += __shfl_down_sync(0xffffffffu, acc, o);
        if (lane == 0) red[wid] = acc;
        CONS_BAR();
        if (tid == 0) {
            float s = 0.0f;
            #pragma unroll
            for (int w = 0; w < 16; ++w) s += red[w];
            out[blockIdx.x] = s + dense_b[blockIdx.x];
        }
    }
}

extern "C" void kernel_launch(void* const* d_in, const int* in_sizes, int n_in,
                              void* d_out, int out_size) {
    const float* x       = (const float*)d_in[0];
    const float* w_ih    = (const float*)d_in[1];
    const float* w_hh    = (const float*)d_in[2];
    const float* b_ih    = (const float*)d_in[3];
    const float* b_hh    = (const float*)d_in[4];
    const float* dense_w = (const float*)d_in[5];
    const float* dense_b = (const float*)d_in[6];

    cudaFuncSetAttribute(lstm_persistent_kernel,
                         cudaFuncAttributeMaxDynamicSharedMemorySize, DSM_BYTES);
    quant_kernel<<<ROWS, 256>>>(w_hh);
    lstm_persistent_kernel<<<NBLK, NTHR, DSM_BYTES>>>(x, w_ih, b_ih, b_hh,
                                                      dense_w, dense_b, (float*)d_out);
}